// round 10
// baseline (speedup 1.0000x reference)
#include <cuda_runtime.h>
#include <math.h>

#define BB 32
#define CC 64
#define HH 128
#define WW 128
#define HW (HH*WW)
#define CHW (CC*HW)
#define NB 3
#define RH 8

#define TS 32
#define HALO 6
#define TL (TS + 2*HALO)   // 44
#define TLP (TL + 1)       // 45: float2 row stride -> conflict-free LDS.64

// scratch (device globals: no allocation allowed)
__device__ float2 g_am[BB*HW];        // interleaved (avg, max)
__device__ float  g_partA[512];
__device__ float  g_partM[512];
__device__ float  g_rw[BB*NB];
__device__ float  g_G[3*HW];          // precomputed xg/yg conv response per branch

// ---------------------------------------------------------------------------
// Kernel A: blocks 0..511: per-pixel channel reduce (avg, max), float4 x 4
// pixels per thread. Blocks 512..575: G maps (xg/yg conv response, data-
// independent FMA work hidden under A's DRAM streaming).
// ---------------------------------------------------------------------------
__global__ __launch_bounds__(256) void kA(
    const float* __restrict__ x,
    const float* __restrict__ dw0, const float* __restrict__ dw1,
    const float* __restrict__ dw2,
    const float* __restrict__ pw0w, const float* __restrict__ pw1w,
    const float* __restrict__ pw2w)
{
    int blk = blockIdx.x;

    if (blk >= 512) {
        // ---- G-map computation ----
        int p = (blk - 512) * 256 + threadIdx.x;     // 0..16383
        int gy = p >> 7, gx = p & 127;

        const float* dws[3] = {dw0, dw1, dw2};
        const float* pws[3] = {pw0w, pw1w, pw2w};
        const int ks[3]  = {3, 7, 7};
        const int dil[3] = {1, 1, 2};

        #pragma unroll
        for (int i = 0; i < 3; ++i) {
            int k = ks[i], d = dil[i], r = k / 2;
            float p2 = pws[i][2], p3 = pws[i][3];
            const float* w2 = dws[i] + 2 * k * k;
            const float* w3 = dws[i] + 3 * k * k;
            float acc = 0.0f;
            for (int dy = 0; dy < k; ++dy) {
                int yy = gy + d * (dy - r);
                if ((unsigned)yy >= (unsigned)HH) continue;
                float yv = -1.0f + (float)yy * (2.0f / 127.0f);
                for (int dx = 0; dx < k; ++dx) {
                    int xx = gx + d * (dx - r);
                    if ((unsigned)xx >= (unsigned)WW) continue;
                    float xv = -1.0f + (float)xx * (2.0f / 127.0f);
                    int t = dy * k + dx;
                    acc += p2 * w2[t] * xv + p3 * w3[t] * yv;
                }
            }
            g_G[i * HW + p] = acc;
        }
        return;
    }

    // ---- channel reduce: 4 pixels/thread ----
    int b = blk >> 4;
    int sp = ((blk & 15) << 10) + threadIdx.x * 4;
    const float4* p = (const float4*)(x + (size_t)b * CHW + sp);

    float4 s = make_float4(0.f, 0.f, 0.f, 0.f);
    float4 m = make_float4(-INFINITY, -INFINITY, -INFINITY, -INFINITY);
    #pragma unroll 16
    for (int c = 0; c < CC; ++c) {
        float4 v = p[c * (HW / 4)];
        s.x += v.x; s.y += v.y; s.z += v.z; s.w += v.w;
        m.x = fmaxf(m.x, v.x); m.y = fmaxf(m.y, v.y);
        m.z = fmaxf(m.z, v.z); m.w = fmaxf(m.w, v.w);
    }
    const float inv64 = 1.0f / 64.0f;
    float4 a = make_float4(s.x * inv64, s.y * inv64, s.z * inv64, s.w * inv64);

    float2* o = g_am + b * HW + sp;
    *(float4*)(o + 0) = make_float4(a.x, m.x, a.y, m.y);
    *(float4*)(o + 2) = make_float4(a.z, m.z, a.w, m.w);

    // deterministic block reduction of (sum avg, sum max)
    float ra = a.x + a.y + a.z + a.w;
    float rm = m.x + m.y + m.z + m.w;
    #pragma unroll
    for (int o2 = 16; o2; o2 >>= 1) {
        ra += __shfl_down_sync(0xffffffffu, ra, o2);
        rm += __shfl_down_sync(0xffffffffu, rm, o2);
    }
    __shared__ float sA[8], sM[8];
    int w = threadIdx.x >> 5, l = threadIdx.x & 31;
    if (l == 0) { sA[w] = ra; sM[w] = rm; }
    __syncthreads();
    if (threadIdx.x == 0) {
        float ta = 0.f, tm = 0.f;
        #pragma unroll
        for (int i = 0; i < 8; ++i) { ta += sA[i]; tm += sM[i]; }
        g_partA[blk] = ta;
        g_partM[blk] = tm;
    }
}

// ---------------------------------------------------------------------------
// Kernel B: finish pooled means + router MLP + softmax -> g_rw[b][3]
// ---------------------------------------------------------------------------
__global__ __launch_bounds__(32) void kB(const float* __restrict__ rw1,
                                         const float* __restrict__ rb1,
                                         const float* __restrict__ rw2,
                                         const float* __restrict__ rb2) {
    int b = blockIdx.x;
    int t = threadIdx.x;
    float a = (t < 16) ? g_partA[b * 16 + t] : 0.0f;
    float m = (t < 16) ? g_partM[b * 16 + t] : 0.0f;
    #pragma unroll
    for (int o = 8; o; o >>= 1) {
        a += __shfl_down_sync(0xffffffffu, a, o);
        m += __shfl_down_sync(0xffffffffu, m, o);
    }
    if (t == 0) {
        float p0 = a * (1.0f / (float)HW);
        float p1 = m * (1.0f / (float)HW);
        // pooled xg, yg are exactly 0 (symmetric linspace)
        float hid[RH];
        #pragma unroll
        for (int j = 0; j < RH; ++j) {
            float h = rw1[j * 4 + 0] * p0 + rw1[j * 4 + 1] * p1 + rb1[j];
            hid[j] = fmaxf(h, 0.0f);
        }
        float lg[NB];
        float mx = -INFINITY;
        #pragma unroll
        for (int i = 0; i < NB; ++i) {
            float s = rb2[i];
            #pragma unroll
            for (int j = 0; j < RH; ++j) s += rw2[i * RH + j] * hid[j];
            lg[i] = s;
            mx = fmaxf(mx, s);
        }
        float den = 0.0f;
        #pragma unroll
        for (int i = 0; i < NB; ++i) { lg[i] = expf(lg[i] - mx); den += lg[i]; }
        float inv = 1.0f / den;
        #pragma unroll
        for (int i = 0; i < NB; ++i) g_rw[b * NB + i] = lg[i] * inv;
    }
}

// ---------------------------------------------------------------------------
// Kernel C (fused): 2-ch convs (router-folded) + G map + sigmoid + apply.
// At block start, every thread issues 8 prefetch.global.L2 covering the
// block's full 256KB x-tile (2048 distinct 128B lines) — DRAM streams x into
// L2 DURING the latency-bound conv phase, so the apply phase reads L2 hits.
// ---------------------------------------------------------------------------
#define DOT2(acc, v, w) \
    acc = fmaf((v).x, (w).x, fmaf((v).y, (w).y, (acc)))

__global__ __launch_bounds__(256, 3) void kC(
    const float* __restrict__ x,
    const float* __restrict__ dw0, const float* __restrict__ dw1, const float* __restrict__ dw2,
    const float* __restrict__ pw0w, const float* __restrict__ pw0b,
    const float* __restrict__ pw1w, const float* __restrict__ pw1b,
    const float* __restrict__ pw2w, const float* __restrict__ pw2b,
    const float* __restrict__ traw,
    float* __restrict__ outY, float* __restrict__ outSA)
{
    __shared__ float2 s2[TL][TLP];
    __shared__ float2 w0s[9], w1s[49], w2s[49];
    __shared__ float4 saS[TS][9];     // [32 rows][8 quads + pad]
    __shared__ float shrw[3];
    __shared__ float shmisc[2];       // bias, invT

    const int b  = blockIdx.z;
    const int x0 = blockIdx.x * TS;
    const int y0 = blockIdx.y * TS;
    const int tid = threadIdx.x;

    // ---- L2 prefetch of this block's x tile (fire-and-forget) ----
    // 2048 lines: line = ch*32 + row; each row-segment of 32 px = one 128B line
    {
        const float* xt = x + (size_t)b * CHW + y0 * WW + x0;
        #pragma unroll
        for (int i = 0; i < 8; ++i) {
            int line = tid + i * 256;
            int ch  = line >> 5;
            int row = line & 31;
            const float* addr = xt + ch * HW + row * WW;
            asm volatile("prefetch.global.L2 [%0];" :: "l"(addr));
        }
    }

    if (tid == 0) {
        shrw[0] = g_rw[b * 3 + 0];
        shrw[1] = g_rw[b * 3 + 1];
        shrw[2] = g_rw[b * 3 + 2];
        float T = log1pf(expf(traw[0])) + 1e-6f;
        shmisc[1] = 1.0f / T;
    }
    __syncthreads();
    const float r0 = shrw[0], r1 = shrw[1], r2 = shrw[2];

    if (tid == 0) {
        shmisc[0] = r0 * pw0b[0] + r1 * pw1b[0] + r2 * pw2b[0];
    }
    // fold router weight * pointwise weight into depthwise taps (ch0=avg, ch1=max)
    if (tid < 9) {
        w0s[tid] = make_float2(r0 * pw0w[0] * dw0[0 * 9 + tid],
                               r0 * pw0w[1] * dw0[1 * 9 + tid]);
    } else if (tid < 58) {
        int i = tid - 9;
        w1s[i] = make_float2(r1 * pw1w[0] * dw1[0 * 49 + i],
                             r1 * pw1w[1] * dw1[1 * 49 + i]);
    } else if (tid < 107) {
        int i = tid - 58;
        w2s[i] = make_float2(r2 * pw2w[0] * dw2[0 * 49 + i],
                             r2 * pw2w[1] * dw2[1 * 49 + i]);
    }

    // load (avg,max) tile with zero halo padding
    const float2* am = g_am + b * HW;
    for (int i = tid; i < TL * TL; i += 256) {
        int ly = i / TL, lx = i % TL;
        int gy = y0 - HALO + ly, gx = x0 - HALO + lx;
        float2 v = make_float2(0.0f, 0.0f);
        if ((unsigned)gy < (unsigned)HH && (unsigned)gx < (unsigned)WW)
            v = am[gy * WW + gx];
        s2[ly][lx] = v;
    }

    // conv phase mapping: lane -> row (conflict-free LDS), warp -> x quad
    const int oy = tid & 31;          // 0..31 (row)
    const int gx8 = tid >> 5;         // 0..7  (x quad, uniform within warp)
    const int ox = gx8 * 4;
    const int cy = oy + HALO;
    const int cx = ox + HALO;

    // G map contribution (global loads, L2-resident) — issue before barrier
    const int pix = (y0 + oy) * WW + x0 + ox;
    float G0[4], G1[4], G2[4];
    #pragma unroll
    for (int j = 0; j < 4; ++j) {
        G0[j] = g_G[0 * HW + pix + j];
        G1[j] = g_G[1 * HW + pix + j];
        G2[j] = g_G[2 * HW + pix + j];
    }

    __syncthreads();

    const float bias = shmisc[0];
    const float invT = shmisc[1];

    float acc0 = bias + r0 * G0[0] + r1 * G1[0] + r2 * G2[0];
    float acc1 = bias + r0 * G0[1] + r1 * G1[1] + r2 * G2[1];
    float acc2 = bias + r0 * G0[2] + r1 * G1[2] + r2 * G2[2];
    float acc3 = bias + r0 * G0[3] + r1 * G1[3] + r2 * G2[3];

    // branch 0: k=3, d=1
    #pragma unroll
    for (int dy = 0; dy < 3; ++dy) {
        const float2* row = s2[cy + dy - 1];
        float2 c[6];
        #pragma unroll
        for (int j = 0; j < 6; ++j) c[j] = row[cx - 1 + j];
        #pragma unroll
        for (int dx = 0; dx < 3; ++dx) {
            float2 w = w0s[dy * 3 + dx];
            DOT2(acc0, c[dx + 0], w);
            DOT2(acc1, c[dx + 1], w);
            DOT2(acc2, c[dx + 2], w);
            DOT2(acc3, c[dx + 3], w);
        }
    }

    // branch 1: k=7, d=1
    #pragma unroll
    for (int dy = 0; dy < 7; ++dy) {
        const float2* row = s2[cy + dy - 3];
        float2 c[10];
        #pragma unroll
        for (int j = 0; j < 10; ++j) c[j] = row[cx - 3 + j];
        #pragma unroll
        for (int dx = 0; dx < 7; ++dx) {
            float2 w = w1s[dy * 7 + dx];
            DOT2(acc0, c[dx + 0], w);
            DOT2(acc1, c[dx + 1], w);
            DOT2(acc2, c[dx + 2], w);
            DOT2(acc3, c[dx + 3], w);
        }
    }

    // branch 2: k=7, d=2 (two chunks to bound live registers)
    #pragma unroll
    for (int ty = 0; ty < 7; ++ty) {
        const float2* row = s2[cy + 2 * (ty - 3)];
        {
            float2 c[8];
            #pragma unroll
            for (int j = 0; j < 8; ++j) c[j] = row[cx - 6 + j];
            #pragma unroll
            for (int tx = 0; tx < 3; ++tx) {
                float2 w = w2s[ty * 7 + tx];
                DOT2(acc0, c[0 + 2 * tx], w);
                DOT2(acc1, c[1 + 2 * tx], w);
                DOT2(acc2, c[2 + 2 * tx], w);
                DOT2(acc3, c[3 + 2 * tx], w);
            }
        }
        {
            float2 c[10];
            #pragma unroll
            for (int j = 0; j < 10; ++j) c[j] = row[cx + j];
            #pragma unroll
            for (int u = 0; u < 4; ++u) {
                float2 w = w2s[ty * 7 + 3 + u];
                DOT2(acc0, c[0 + 2 * u], w);
                DOT2(acc1, c[1 + 2 * u], w);
                DOT2(acc2, c[2 + 2 * u], w);
                DOT2(acc3, c[3 + 2 * u], w);
            }
        }
    }

    float4 sa;
    sa.x = 1.0f / (1.0f + __expf(-acc0 * invT));
    sa.y = 1.0f / (1.0f + __expf(-acc1 * invT));
    sa.z = 1.0f / (1.0f + __expf(-acc2 * invT));
    sa.w = 1.0f / (1.0f + __expf(-acc3 * invT));
    saS[oy][gx8] = sa;

    __syncthreads();

    // apply phase mapping: lanes -> contiguous x for coalesced global access
    const int py = tid >> 3;
    const int xq = tid & 7;
    float4 sv = saS[py][xq];
    const int base = (y0 + py) * WW + x0 + xq * 4;

    *(float4*)(outSA + b * HW + base) = sv;

    const float* xb = x + (size_t)b * CHW + base;
    float* yb = outY + (size_t)b * CHW + base;
    #pragma unroll 16
    for (int c = 0; c < CC; ++c) {
        float4 v = *(const float4*)(xb + c * HW);
        v.x *= sv.x; v.y *= sv.y; v.z *= sv.z; v.w *= sv.w;
        *(float4*)(yb + c * HW) = v;
    }
}

// ---------------------------------------------------------------------------
extern "C" void kernel_launch(void* const* d_in, const int* in_sizes, int n_in,
                              void* d_out, int out_size) {
    const float* x    = (const float*)d_in[0];
    const float* dw0  = (const float*)d_in[1];
    const float* dw1  = (const float*)d_in[2];
    const float* dw2  = (const float*)d_in[3];
    const float* pw0w = (const float*)d_in[4];
    const float* pw0b = (const float*)d_in[5];
    const float* pw1w = (const float*)d_in[6];
    const float* pw1b = (const float*)d_in[7];
    const float* pw2w = (const float*)d_in[8];
    const float* pw2b = (const float*)d_in[9];
    const float* rw1  = (const float*)d_in[10];
    const float* rb1  = (const float*)d_in[11];
    const float* rw2  = (const float*)d_in[12];
    const float* rb2  = (const float*)d_in[13];
    const float* traw = (const float*)d_in[14];

    float* outY  = (float*)d_out;
    float* outSA = (float*)d_out + (size_t)BB * CHW;

    kA<<<576, 256>>>(x, dw0, dw1, dw2, pw0w, pw1w, pw2w);
    kB<<<32, 32>>>(rw1, rb1, rw2, rb2);
    dim3 gc(WW / TS, HH / TS, BB);
    kC<<<gc, 256>>>(x, dw0, dw1, dw2, pw0w, pw0b, pw1w, pw1b, pw2w, pw2b,
                    traw, outY, outSA);
}

// round 11
// speedup vs baseline: 1.3427x; 1.3427x over previous
#include <cuda_runtime.h>
#include <math.h>

#define BB 32
#define CC 64
#define HH 128
#define WW 128
#define HW (HH*WW)
#define CHW (CC*HW)
#define NB 3
#define RH 8

#define TS 32
#define HALO 6
#define TL (TS + 2*HALO)   // 44
#define TLP (TL + 1)       // 45: float2 row stride -> conflict-free LDS.64

#define NRED 2048          // reduce blocks in kA

// scratch (device globals: no allocation allowed)
__device__ float2 g_am[BB*HW];        // interleaved (avg, max)
__device__ float  g_partA[NRED];
__device__ float  g_partM[NRED];
__device__ float  g_rw[BB*NB];
__device__ float  g_G[3*HW];          // precomputed xg/yg conv response per branch
__device__ unsigned g_cnt = 0;        // last-block counter (reset in-kernel)

// ---------------------------------------------------------------------------
// Kernel A: blocks 0..2047: per-pixel channel reduce (avg, max), 1 px/thread
// (r1 shape: best measured occupancy/BW). Blocks 2048..2111: G maps.
// The LAST reduce block (threadfence+atomic) also computes the router MLP
// (former kB) — deterministic: it reduces fully-written partials.
// ---------------------------------------------------------------------------
__global__ __launch_bounds__(256) void kA(
    const float* __restrict__ x,
    const float* __restrict__ dw0, const float* __restrict__ dw1,
    const float* __restrict__ dw2,
    const float* __restrict__ pw0w, const float* __restrict__ pw1w,
    const float* __restrict__ pw2w,
    const float* __restrict__ rw1, const float* __restrict__ rb1,
    const float* __restrict__ rw2, const float* __restrict__ rb2)
{
    int blk = blockIdx.x;
    int tid = threadIdx.x;

    if (blk >= NRED) {
        // ---- G-map computation (data-independent xg/yg conv response) ----
        int p = (blk - NRED) * 256 + tid;            // 0..16383
        int gy = p >> 7, gx = p & 127;

        const float* dws[3] = {dw0, dw1, dw2};
        const float* pws[3] = {pw0w, pw1w, pw2w};
        const int ks[3]  = {3, 7, 7};
        const int dil[3] = {1, 1, 2};

        #pragma unroll
        for (int i = 0; i < 3; ++i) {
            int k = ks[i], d = dil[i], r = k / 2;
            float p2 = pws[i][2], p3 = pws[i][3];
            const float* w2 = dws[i] + 2 * k * k;
            const float* w3 = dws[i] + 3 * k * k;
            float acc = 0.0f;
            for (int dy = 0; dy < k; ++dy) {
                int yy = gy + d * (dy - r);
                if ((unsigned)yy >= (unsigned)HH) continue;
                float yv = -1.0f + (float)yy * (2.0f / 127.0f);
                for (int dx = 0; dx < k; ++dx) {
                    int xx = gx + d * (dx - r);
                    if ((unsigned)xx >= (unsigned)WW) continue;
                    float xv = -1.0f + (float)xx * (2.0f / 127.0f);
                    int t = dy * k + dx;
                    acc += p2 * w2[t] * xv + p3 * w3[t] * yv;
                }
            }
            g_G[i * HW + p] = acc;
        }
        return;
    }

    // ---- channel reduce: 1 pixel/thread, scalar coalesced loads ----
    int b = blk >> 6;
    int sp = ((blk & 63) << 8) + tid;
    const float* p = x + (size_t)b * CHW + sp;

    float s = 0.0f, m = -INFINITY;
    #pragma unroll 16
    for (int c = 0; c < CC; ++c) {
        float v = p[c * HW];
        s += v;
        m = fmaxf(m, v);
    }
    float av = s * (1.0f / 64.0f);
    g_am[b * HW + sp] = make_float2(av, m);

    // deterministic block reduction of (sum of avg, sum of max)
    float ra = av, rm = m;
    #pragma unroll
    for (int o = 16; o; o >>= 1) {
        ra += __shfl_down_sync(0xffffffffu, ra, o);
        rm += __shfl_down_sync(0xffffffffu, rm, o);
    }
    __shared__ float sA[8], sM[8];
    int w = tid >> 5, l = tid & 31;
    if (l == 0) { sA[w] = ra; sM[w] = rm; }
    __syncthreads();

    __shared__ bool amLast;
    if (tid == 0) {
        float ta = 0.f, tm = 0.f;
        #pragma unroll
        for (int i = 0; i < 8; ++i) { ta += sA[i]; tm += sM[i]; }
        g_partA[blk] = ta;
        g_partM[blk] = tm;
        __threadfence();
        amLast = (atomicAdd(&g_cnt, 1u) == NRED - 1);
    }
    __syncthreads();
    if (!amLast) return;

    if (tid == 0) g_cnt = 0;   // reset for next graph replay

    // ---- router (former kB), by the designated last block ----
    // thread t: batch = t>>3, lane-octet j = t&7 sums 8 partials
    int batch = tid >> 3;
    int j = tid & 7;
    float a = 0.f, mm = 0.f;
    #pragma unroll
    for (int i = 0; i < 8; ++i) {
        int idx = batch * 64 + j * 8 + i;
        a  += g_partA[idx];
        mm += g_partM[idx];
    }
    #pragma unroll
    for (int o = 4; o; o >>= 1) {
        a  += __shfl_down_sync(0xffffffffu, a,  o, 8);
        mm += __shfl_down_sync(0xffffffffu, mm, o, 8);
    }
    __shared__ float bA[32], bM[32];
    if (j == 0) { bA[batch] = a; bM[batch] = mm; }
    __syncthreads();

    if (tid < 32) {
        float p0 = bA[tid] * (1.0f / (float)HW);
        float p1 = bM[tid] * (1.0f / (float)HW);
        // pooled xg, yg are exactly 0 (symmetric linspace)
        float hid[RH];
        #pragma unroll
        for (int jj = 0; jj < RH; ++jj) {
            float h = rw1[jj * 4 + 0] * p0 + rw1[jj * 4 + 1] * p1 + rb1[jj];
            hid[jj] = fmaxf(h, 0.0f);
        }
        float lg[NB];
        float mx = -INFINITY;
        #pragma unroll
        for (int i = 0; i < NB; ++i) {
            float ss = rb2[i];
            #pragma unroll
            for (int jj = 0; jj < RH; ++jj) ss += rw2[i * RH + jj] * hid[jj];
            lg[i] = ss;
            mx = fmaxf(mx, ss);
        }
        float den = 0.0f;
        #pragma unroll
        for (int i = 0; i < NB; ++i) { lg[i] = expf(lg[i] - mx); den += lg[i]; }
        float inv = 1.0f / den;
        #pragma unroll
        for (int i = 0; i < NB; ++i) g_rw[tid * NB + i] = lg[i] * inv;
    }
}

// ---------------------------------------------------------------------------
// Kernel C (fused): 2-ch convs (router-folded) + G map + sigmoid + apply.
// Exact r4 body (best measured: 55.2us).
// ---------------------------------------------------------------------------
#define DOT2(acc, v, w) \
    acc = fmaf((v).x, (w).x, fmaf((v).y, (w).y, (acc)))

__global__ __launch_bounds__(256, 3) void kC(
    const float* __restrict__ x,
    const float* __restrict__ dw0, const float* __restrict__ dw1, const float* __restrict__ dw2,
    const float* __restrict__ pw0w, const float* __restrict__ pw0b,
    const float* __restrict__ pw1w, const float* __restrict__ pw1b,
    const float* __restrict__ pw2w, const float* __restrict__ pw2b,
    const float* __restrict__ traw,
    float* __restrict__ outY, float* __restrict__ outSA)
{
    __shared__ float2 s2[TL][TLP];
    __shared__ float2 w0s[9], w1s[49], w2s[49];
    __shared__ float4 saS[TS][9];     // [32 rows][8 quads + pad]
    __shared__ float shrw[3];
    __shared__ float shmisc[2];       // bias, invT

    const int b  = blockIdx.z;
    const int x0 = blockIdx.x * TS;
    const int y0 = blockIdx.y * TS;
    const int tid = threadIdx.x;

    if (tid == 0) {
        shrw[0] = g_rw[b * 3 + 0];
        shrw[1] = g_rw[b * 3 + 1];
        shrw[2] = g_rw[b * 3 + 2];
        float T = log1pf(expf(traw[0])) + 1e-6f;
        shmisc[1] = 1.0f / T;
    }
    __syncthreads();
    const float r0 = shrw[0], r1 = shrw[1], r2 = shrw[2];

    if (tid == 0) {
        shmisc[0] = r0 * pw0b[0] + r1 * pw1b[0] + r2 * pw2b[0];
    }
    // fold router weight * pointwise weight into depthwise taps (ch0=avg, ch1=max)
    if (tid < 9) {
        w0s[tid] = make_float2(r0 * pw0w[0] * dw0[0 * 9 + tid],
                               r0 * pw0w[1] * dw0[1 * 9 + tid]);
    } else if (tid < 58) {
        int i = tid - 9;
        w1s[i] = make_float2(r1 * pw1w[0] * dw1[0 * 49 + i],
                             r1 * pw1w[1] * dw1[1 * 49 + i]);
    } else if (tid < 107) {
        int i = tid - 58;
        w2s[i] = make_float2(r2 * pw2w[0] * dw2[0 * 49 + i],
                             r2 * pw2w[1] * dw2[1 * 49 + i]);
    }

    // load (avg,max) tile with zero halo padding
    const float2* am = g_am + b * HW;
    for (int i = tid; i < TL * TL; i += 256) {
        int ly = i / TL, lx = i % TL;
        int gy = y0 - HALO + ly, gx = x0 - HALO + lx;
        float2 v = make_float2(0.0f, 0.0f);
        if ((unsigned)gy < (unsigned)HH && (unsigned)gx < (unsigned)WW)
            v = am[gy * WW + gx];
        s2[ly][lx] = v;
    }

    // conv phase mapping: lane -> row (conflict-free LDS), warp -> x quad
    const int oy = tid & 31;          // 0..31 (row)
    const int gx8 = tid >> 5;         // 0..7  (x quad, uniform within warp)
    const int ox = gx8 * 4;
    const int cy = oy + HALO;
    const int cx = ox + HALO;

    // G map contribution (global loads, L2-resident) — issue before barrier
    const int pix = (y0 + oy) * WW + x0 + ox;
    float G0[4], G1[4], G2[4];
    #pragma unroll
    for (int j = 0; j < 4; ++j) {
        G0[j] = g_G[0 * HW + pix + j];
        G1[j] = g_G[1 * HW + pix + j];
        G2[j] = g_G[2 * HW + pix + j];
    }

    __syncthreads();

    const float bias = shmisc[0];
    const float invT = shmisc[1];

    float acc0 = bias + r0 * G0[0] + r1 * G1[0] + r2 * G2[0];
    float acc1 = bias + r0 * G0[1] + r1 * G1[1] + r2 * G2[1];
    float acc2 = bias + r0 * G0[2] + r1 * G1[2] + r2 * G2[2];
    float acc3 = bias + r0 * G0[3] + r1 * G1[3] + r2 * G2[3];

    // branch 0: k=3, d=1
    #pragma unroll
    for (int dy = 0; dy < 3; ++dy) {
        const float2* row = s2[cy + dy - 1];
        float2 c[6];
        #pragma unroll
        for (int j = 0; j < 6; ++j) c[j] = row[cx - 1 + j];
        #pragma unroll
        for (int dx = 0; dx < 3; ++dx) {
            float2 w = w0s[dy * 3 + dx];
            DOT2(acc0, c[dx + 0], w);
            DOT2(acc1, c[dx + 1], w);
            DOT2(acc2, c[dx + 2], w);
            DOT2(acc3, c[dx + 3], w);
        }
    }

    // branch 1: k=7, d=1
    #pragma unroll
    for (int dy = 0; dy < 7; ++dy) {
        const float2* row = s2[cy + dy - 3];
        float2 c[10];
        #pragma unroll
        for (int j = 0; j < 10; ++j) c[j] = row[cx - 3 + j];
        #pragma unroll
        for (int dx = 0; dx < 7; ++dx) {
            float2 w = w1s[dy * 7 + dx];
            DOT2(acc0, c[dx + 0], w);
            DOT2(acc1, c[dx + 1], w);
            DOT2(acc2, c[dx + 2], w);
            DOT2(acc3, c[dx + 3], w);
        }
    }

    // branch 2: k=7, d=2 (two chunks to bound live registers)
    #pragma unroll
    for (int ty = 0; ty < 7; ++ty) {
        const float2* row = s2[cy + 2 * (ty - 3)];
        {
            float2 c[8];
            #pragma unroll
            for (int j = 0; j < 8; ++j) c[j] = row[cx - 6 + j];
            #pragma unroll
            for (int tx = 0; tx < 3; ++tx) {
                float2 w = w2s[ty * 7 + tx];
                DOT2(acc0, c[0 + 2 * tx], w);
                DOT2(acc1, c[1 + 2 * tx], w);
                DOT2(acc2, c[2 + 2 * tx], w);
                DOT2(acc3, c[3 + 2 * tx], w);
            }
        }
        {
            float2 c[10];
            #pragma unroll
            for (int j = 0; j < 10; ++j) c[j] = row[cx + j];
            #pragma unroll
            for (int u = 0; u < 4; ++u) {
                float2 w = w2s[ty * 7 + 3 + u];
                DOT2(acc0, c[0 + 2 * u], w);
                DOT2(acc1, c[1 + 2 * u], w);
                DOT2(acc2, c[2 + 2 * u], w);
                DOT2(acc3, c[3 + 2 * u], w);
            }
        }
    }

    float4 sa;
    sa.x = 1.0f / (1.0f + __expf(-acc0 * invT));
    sa.y = 1.0f / (1.0f + __expf(-acc1 * invT));
    sa.z = 1.0f / (1.0f + __expf(-acc2 * invT));
    sa.w = 1.0f / (1.0f + __expf(-acc3 * invT));
    saS[oy][gx8] = sa;

    __syncthreads();

    // apply phase mapping: lanes -> contiguous x for coalesced global access
    const int py = tid >> 3;
    const int xq = tid & 7;
    float4 sv = saS[py][xq];
    const int base = (y0 + py) * WW + x0 + xq * 4;

    *(float4*)(outSA + b * HW + base) = sv;

    const float* xb = x + (size_t)b * CHW + base;
    float* yb = outY + (size_t)b * CHW + base;
    #pragma unroll 16
    for (int c = 0; c < CC; ++c) {
        float4 v = *(const float4*)(xb + c * HW);
        v.x *= sv.x; v.y *= sv.y; v.z *= sv.z; v.w *= sv.w;
        *(float4*)(yb + c * HW) = v;
    }
}

// ---------------------------------------------------------------------------
extern "C" void kernel_launch(void* const* d_in, const int* in_sizes, int n_in,
                              void* d_out, int out_size) {
    const float* x    = (const float*)d_in[0];
    const float* dw0  = (const float*)d_in[1];
    const float* dw1  = (const float*)d_in[2];
    const float* dw2  = (const float*)d_in[3];
    const float* pw0w = (const float*)d_in[4];
    const float* pw0b = (const float*)d_in[5];
    const float* pw1w = (const float*)d_in[6];
    const float* pw1b = (const float*)d_in[7];
    const float* pw2w = (const float*)d_in[8];
    const float* pw2b = (const float*)d_in[9];
    const float* rw1  = (const float*)d_in[10];
    const float* rb1  = (const float*)d_in[11];
    const float* rw2  = (const float*)d_in[12];
    const float* rb2  = (const float*)d_in[13];
    const float* traw = (const float*)d_in[14];

    float* outY  = (float*)d_out;
    float* outSA = (float*)d_out + (size_t)BB * CHW;

    kA<<<NRED + 64, 256>>>(x, dw0, dw1, dw2, pw0w, pw1w, pw2w,
                           rw1, rb1, rw2, rb2);
    dim3 gc(WW / TS, HH / TS, BB);
    kC<<<gc, 256>>>(x, dw0, dw1, dw2, pw0w, pw0b, pw1w, pw1b, pw2w, pw2b,
                    traw, outY, outSA);
}